// round 12
// baseline (speedup 1.0000x reference)
#include <cuda_runtime.h>
#include <cuda_fp16.h>
#include <mma.h>
using namespace nvcuda;

#define N_NODES 50000
#define N_EDGES 800000
#define HID 128
#define N_GRAPHS 64
#define CAP 64          // padded CSR bucket capacity (P(deg>=64) ~ 1e-18)

// ---------------- scratch (static device globals; no allocation) ----------
__device__ float  g_bufB[N_NODES * HID];         // h2 (fp32)
__device__ __half g_hs[(N_NODES + 1) * HID];     // dinv_i*h1_i (fp16) + zero row
__device__ __half g_hA[(N_NODES + 64) * HID];    // aggregated h1 (fp16), row-padded
__device__ __half g_W2h[HID * HID];              // W2 hi (fp16)
__device__ __half g_W2l[HID * HID];              // W2 residual (fp16)
__device__ float  g_xs[(N_NODES + 1) * 16];      // dinv_i*x_i + zero row
__device__ float  g_xa[N_NODES * 16];            // aggregated, di-scaled x
__device__ int    g_cur[N_NODES];                // in-degree (atomic bump)
__device__ int    g_csr[N_NODES * CAP];          // padded buckets of source ids
__device__ float  g_dinv[N_NODES];
__device__ float  g_pool[N_GRAPHS * HID];
__device__ int    g_gcnt[N_GRAPHS];
__device__ int    g_is64;

// ---------------- helpers ---------------------------------------------------
__device__ __forceinline__ int ld_idx(const void* p, long long i, int is64) {
    if (is64) return (int)((const long long*)p)[i];
    return ((const int*)p)[i];
}

__device__ __forceinline__ float4 h4_to_f4(unsigned int a, unsigned int b) {
    float2 p = __half22float2(*(const __half2*)&a);
    float2 q = __half22float2(*(const __half2*)&b);
    return make_float4(p.x, p.y, q.x, q.y);
}

// local int64/int32 detection from the first 64 index values (deterministic)
__device__ __forceinline__ int detect64(const void* ei, int tid, int* s_flag) {
    if (tid == 0) *s_flag = 1;
    __syncthreads();
    if (tid < 64) {
        long long v = ((const long long*)ei)[tid];
        if (v < 0 || v >= N_NODES) *s_flag = 0;
    }
    __syncthreads();
    return *s_flag;
}

// ---------------- kernels ---------------------------------------------------
__global__ void k_init() {
    int i = blockIdx.x * blockDim.x + threadIdx.x;
    if (i < N_NODES) g_cur[i] = 0;
    if (i < N_GRAPHS * HID) g_pool[i] = 0.f;
    if (i < N_GRAPHS) g_gcnt[i] = 0;
    if (i < 16) g_xs[N_NODES * 16 + i] = 0.f;           // zero sentinel row
    if (i < HID) g_hs[N_NODES * HID + i] = __float2half(0.f);
}

// single-pass padded-bucket CSR build
__global__ void k_build(const void* ei) {
    __shared__ int s_is64;
    int tid = threadIdx.x;
    int is64 = detect64(ei, tid, &s_is64);
    int e = blockIdx.x * blockDim.x + tid;
    if (e < N_EDGES) {
        int s = ld_idx(ei, e, is64);
        int d = ld_idx(ei, (long long)N_EDGES + e, is64);
        int slot = atomicAdd(&g_cur[d], 1);
        if (slot < CAP) g_csr[d * CAP + slot] = s;
    }
    if (blockIdx.x == 0 && tid == 0) g_is64 = is64;
}

// dinv + pre-scaled features xs = dinv_i * x_i; also split W2 -> fp16 hi/lo
__global__ void k_dinvxs(const float* __restrict__ x, const float* __restrict__ W2) {
    int t = blockIdx.x * blockDim.x + threadIdx.x;
    if (t < HID * HID) {
        float w = W2[t];
        __half h = __float2half_rn(w);
        g_W2h[t] = h;
        g_W2l[t] = __float2half_rn(w - __half2float(h));
    }
    int i = t >> 4;                 // node
    int col = t & 15;
    if (i >= N_NODES) return;
    float di = rsqrtf((float)(g_cur[i] + 1));   // +1 self-loop
    if (col == 0) g_dinv[i] = di;
    g_xs[i * 16 + col] = x[i * 16 + col] * di;
}

// Pure gather for layer 1: xa_i = di*(xs[i] + sum_e xs[s]).
// One warp per node; 8 edge-groups of 4 lanes, float4 per lane.
__global__ void k_aggx() {
    int i = (blockIdx.x * blockDim.x + threadIdx.x) >> 5;
    if (i >= N_NODES) return;
    int lane = threadIdx.x & 31;
    int grp = lane >> 2;    // 0..7 edge group
    int sub = lane & 3;     // float4 slot within 16-float row
    float di = g_dinv[i];
    const float4* xs4 = (const float4*)g_xs;

    float4 acc = (grp == 0) ? xs4[i * 4 + sub]
                            : make_float4(0.f, 0.f, 0.f, 0.f);   // self term
    int base = i * CAP;
    int deg = min(g_cur[i], CAP);
    for (int e = 0; e < deg; e += 8) {
        int idx = e + grp;
        int s = (idx < deg) ? g_csr[base + idx] : N_NODES;   // sentinel -> 0
        float4 v = xs4[s * 4 + sub];
        acc.x += v.x; acc.y += v.y; acc.z += v.z; acc.w += v.w;
    }
    #pragma unroll
    for (int off = 4; off < 32; off <<= 1) {
        acc.x += __shfl_xor_sync(0xffffffffu, acc.x, off);
        acc.y += __shfl_xor_sync(0xffffffffu, acc.y, off);
        acc.z += __shfl_xor_sync(0xffffffffu, acc.z, off);
        acc.w += __shfl_xor_sync(0xffffffffu, acc.w, off);
    }
    if (grp == 0) {
        acc.x *= di; acc.y *= di; acc.z *= di; acc.w *= di;
        ((float4*)g_xa)[i * 4 + sub] = acc;
    }
}

// Tiled layer-1 GEMM: hs = di * relu(xa @ W1 + b1), fp16 out.
// 32 rows/block, 128 threads (one output col each).
__global__ void __launch_bounds__(128) k_gemm1(const float* __restrict__ W1,
                                               const float* __restrict__ b1) {
    __shared__ float W1s[16 * 128];
    __shared__ float xas[32 * 16];
    __shared__ float dis[32];
    int tid = threadIdx.x;
    int row0 = blockIdx.x * 32;
    {   // W1: 2048 floats = 512 float4 / 128 threads
        float4* d4 = (float4*)W1s;
        const float4* s4 = (const float4*)W1;
        #pragma unroll
        for (int j = 0; j < 4; j++) d4[tid + 128 * j] = s4[tid + 128 * j];
    }
    {   // xa tile: 32 rows x 16 = 128 float4
        float4* d4 = (float4*)xas;
        const float4* s4 = (const float4*)g_xa;
        int r = row0 * 4 + tid;
        d4[tid] = (r < N_NODES * 4) ? s4[r] : make_float4(0.f, 0.f, 0.f, 0.f);
    }
    if (tid < 32) {
        int r = row0 + tid;
        dis[tid] = (r < N_NODES) ? g_dinv[r] : 0.f;
    }
    __syncthreads();

    float w[16];
    #pragma unroll
    for (int k = 0; k < 16; k++) w[k] = W1s[k * 128 + tid];
    float bias = b1[tid];
    int rmax = min(32, N_NODES - row0);
    for (int r = 0; r < rmax; r++) {
        float acc = bias;
        #pragma unroll
        for (int k = 0; k < 16; k++) acc = fmaf(xas[r * 16 + k], w[k], acc);
        float hsv = fmaxf(acc, 0.f) * dis[r];       // hs = di * relu(h1)
        g_hs[(row0 + r) * 128 + tid] = __float2half(hsv);
    }
}

// Aggregate hs (fp16): hA_i = di * (hs[i] + sum_e hs[s]), fp16 out.
// One warp per node; 2 edge-groups of 16 lanes, uint4 (8 halves) per lane.
__global__ void k_aggh() {
    int i = (blockIdx.x * blockDim.x + threadIdx.x) >> 5;
    if (i >= N_NODES) return;
    int lane = threadIdx.x & 31;
    int grp = lane >> 4;    // 0..1
    int sub = lane & 15;    // uint4 slot within 128-half row
    float di = g_dinv[i];
    const uint4* __restrict__ h = (const uint4*)g_hs;

    float4 a0, a1;
    if (grp == 0) {         // self term
        uint4 sv = h[i * 16 + sub];
        a0 = h4_to_f4(sv.x, sv.y);
        a1 = h4_to_f4(sv.z, sv.w);
    } else {
        a0 = make_float4(0.f, 0.f, 0.f, 0.f);
        a1 = make_float4(0.f, 0.f, 0.f, 0.f);
    }

    int base = i * CAP;
    int deg = min(g_cur[i], CAP);
    for (int e = 0; e < deg; e += 4) {
        int i0 = e + grp;
        int i1 = e + grp + 2;
        int s0 = (i0 < deg) ? g_csr[base + i0] : N_NODES;
        int s1 = (i1 < deg) ? g_csr[base + i1] : N_NODES;
        uint4 v0 = h[s0 * 16 + sub];
        uint4 v1 = h[s1 * 16 + sub];
        float4 f00 = h4_to_f4(v0.x, v0.y);
        float4 f01 = h4_to_f4(v0.z, v0.w);
        float4 f10 = h4_to_f4(v1.x, v1.y);
        float4 f11 = h4_to_f4(v1.z, v1.w);
        a0.x += f00.x + f10.x; a0.y += f00.y + f10.y;
        a0.z += f00.z + f10.z; a0.w += f00.w + f10.w;
        a1.x += f01.x + f11.x; a1.y += f01.y + f11.y;
        a1.z += f01.z + f11.z; a1.w += f01.w + f11.w;
    }
    // combine the 2 groups
    a0.x += __shfl_xor_sync(0xffffffffu, a0.x, 16);
    a0.y += __shfl_xor_sync(0xffffffffu, a0.y, 16);
    a0.z += __shfl_xor_sync(0xffffffffu, a0.z, 16);
    a0.w += __shfl_xor_sync(0xffffffffu, a0.w, 16);
    a1.x += __shfl_xor_sync(0xffffffffu, a1.x, 16);
    a1.y += __shfl_xor_sync(0xffffffffu, a1.y, 16);
    a1.z += __shfl_xor_sync(0xffffffffu, a1.z, 16);
    a1.w += __shfl_xor_sync(0xffffffffu, a1.w, 16);

    a0.x *= di; a0.y *= di; a0.z *= di; a0.w *= di;
    a1.x *= di; a1.y *= di; a1.z *= di; a1.w *= di;
    // pack 4 floats -> 4 halves (uint2) and store slot 2*sub+grp
    float4 v = (grp == 0) ? a0 : a1;
    __half2 lo = __floats2half2_rn(v.x, v.y);
    __half2 hi = __floats2half2_rn(v.z, v.w);
    uint2 pk;
    pk.x = *(const unsigned int*)&lo;
    pk.y = *(const unsigned int*)&hi;
    ((uint2*)g_hA)[i * 32 + 2 * sub + grp] = pk;
}

// h2 = relu(hA @ (W2h + W2l) + b2) -> bufB via tensor cores (wmma fp16, f32 acc).
// Block: 64 rows x 128 cols, 8 warps in 4x2 grid; each warp 16 rows x 64 cols.
__global__ void __launch_bounds__(256) k_gemm2w(const float* __restrict__ b2) {
    __shared__ float Cs[64 * 128];
    int tid = threadIdx.x;
    int wid = tid >> 5;
    int wr = wid >> 1;          // 0..3 warp row
    int wc = wid & 1;           // 0..1 warp col
    int row0 = blockIdx.x * 64;

    wmma::fragment<wmma::accumulator, 16, 16, 16, float> acc[4];
    #pragma unroll
    for (int c = 0; c < 4; c++) wmma::fill_fragment(acc[c], 0.f);

    const __half* A = g_hA + (row0 + wr * 16) * HID;
    for (int k = 0; k < HID; k += 16) {
        wmma::fragment<wmma::matrix_a, 16, 16, 16, __half, wmma::row_major> a;
        wmma::load_matrix_sync(a, A + k, HID);
        #pragma unroll
        for (int c = 0; c < 4; c++) {
            int col = wc * 64 + c * 16;
            wmma::fragment<wmma::matrix_b, 16, 16, 16, __half, wmma::row_major> b;
            wmma::load_matrix_sync(b, g_W2h + k * HID + col, HID);
            wmma::mma_sync(acc[c], a, b, acc[c]);
            wmma::load_matrix_sync(b, g_W2l + k * HID + col, HID);
            wmma::mma_sync(acc[c], a, b, acc[c]);
        }
    }
    #pragma unroll
    for (int c = 0; c < 4; c++)
        wmma::store_matrix_sync(&Cs[(wr * 16) * 128 + wc * 64 + c * 16],
                                acc[c], 128, wmma::mem_row_major);
    __syncthreads();

    // bias + relu + store (64 rows x 32 float4)
    for (int idx = tid; idx < 64 * 32; idx += 256) {
        int r = idx >> 5;
        int c4 = idx & 31;
        int row = row0 + r;
        if (row < N_NODES) {
            float4 v = ((const float4*)Cs)[idx];
            float4 bb = ((const float4*)b2)[c4];
            v.x = fmaxf(v.x + bb.x, 0.f);
            v.y = fmaxf(v.y + bb.y, 0.f);
            v.z = fmaxf(v.z + bb.z, 0.f);
            v.w = fmaxf(v.w + bb.w, 0.f);
            ((float4*)g_bufB)[row * 32 + c4] = v;
        }
    }
}

// pool sums from bufB (batch sorted -> local accumulation); also graph counts.
// 32 nodes per block -> short serial chains.
__global__ void k_pool(const void* batch) {
    int tid = threadIdx.x;
    int start = blockIdx.x * 32;
    int end = min(start + 32, N_NODES);
    if (start >= N_NODES) return;
    int is64 = g_is64;
    int curg = ld_idx(batch, start, is64);
    float acc = 0.f;
    int runlen = 0;
    for (int n = start; n < end; n++) {
        int g = ld_idx(batch, n, is64);
        if (g != curg) {
            atomicAdd(&g_pool[curg * 128 + tid], acc);
            if (tid == 0) atomicAdd(&g_gcnt[curg], runlen);
            acc = 0.f; runlen = 0;
            curg = g;
        }
        acc += g_bufB[n * 128 + tid];
        runlen++;
    }
    atomicAdd(&g_pool[curg * 128 + tid], acc);
    if (tid == 0) atomicAdd(&g_gcnt[curg], runlen);
}

__global__ void k_final(const float* __restrict__ Wfc,
                        const float* __restrict__ bfc,
                        float* __restrict__ out) {
    int tid = threadIdx.x;   // 1024 = 64*16
    int g = tid >> 4;
    int o = tid & 15;
    float c = (float)max(g_gcnt[g], 1);
    float s = 0.f;
    #pragma unroll 8
    for (int k = 0; k < 128; k++)
        s = fmaf(g_pool[g * 128 + k], Wfc[k * 16 + o], s);
    out[tid] = s / c + bfc[o];
}

// ---------------- launch ----------------------------------------------------
extern "C" void kernel_launch(void* const* d_in, const int* in_sizes, int n_in,
                              void* d_out, int out_size) {
    const float* x   = (const float*)d_in[0];
    const void*  ei  = d_in[1];
    const void*  bat = d_in[2];
    const float* W1  = (const float*)d_in[3];
    const float* b1  = (const float*)d_in[4];
    const float* W2  = (const float*)d_in[5];
    const float* b2  = (const float*)d_in[6];
    const float* Wfc = (const float*)d_in[7];
    const float* bfc = (const float*)d_in[8];
    float* out = (float*)d_out;

    k_init<<<(N_NODES + 255) / 256, 256>>>();                 // 1
    k_build<<<(N_EDGES + 255) / 256, 256>>>(ei);              // 2
    k_dinvxs<<<(N_NODES * 16 + 255) / 256, 256>>>(x, W2);     // 3
    k_aggx<<<(N_NODES * 32 + 255) / 256, 256>>>();            // 4  <- ncu slot
    k_gemm1<<<(N_NODES + 31) / 32, 128>>>(W1, b1);            // 5
    k_aggh<<<(N_NODES + 7) / 8, 256>>>();                     // 6
    k_gemm2w<<<(N_NODES + 63) / 64, 256>>>(b2);               // 7
    k_pool<<<(N_NODES + 31) / 32, 128>>>(bat);                // 8
    k_final<<<1, 1024>>>(Wfc, bfc, out);                      // 9
}